// round 1
// baseline (speedup 1.0000x reference)
#include <cuda_runtime.h>
#include <cuda_bf16.h>

#define NODES 100000
#define EDGES_MAX 1600000
#define F_HID 128
#define F_OUT 64

// ---------------- scratch (device globals: allocation-free) ----------------
__device__ int   g_is64;
__device__ int   g_cnt[NODES];
__device__ int   g_cursor[NODES];
__device__ int   g_rowptr[NODES];
__device__ float g_dinv[NODES];
__device__ int   g_csr[EDGES_MAX];
__device__ float g_hs1[(size_t)NODES * F_HID];   // dinv * (x @ W1)
__device__ float g_y1 [(size_t)NODES * F_HID];   // relu(agg1 + b1)
__device__ float g_hs2[(size_t)NODES * F_OUT];   // dinv * (y1 @ W2)
__device__ int   g_bsum[128];
__device__ int   g_boff[128];

// ---------------- dtype detection: int64 vs int32 edge_index ----------------
// For an int64 array of nonneg values < 100000, every odd 32-bit word is 0.
// For int32 random values in [0,1e5), P(word==0) = 1e-5 -> 1024 in a row ~ impossible.
__global__ void k_detect(const unsigned int* __restrict__ w) {
    __shared__ int ok;
    if (threadIdx.x == 0) ok = 1;
    __syncthreads();
    int bad = 0;
    for (int i = threadIdx.x; i < 1024; i += blockDim.x)
        if (w[2 * i + 1] != 0u) bad = 1;
    if (bad) atomicAnd(&ok, 0);
    __syncthreads();
    if (threadIdx.x == 0) g_is64 = ok;
}

__device__ __forceinline__ void get_edge(const void* ei, int E, int e, int is64,
                                         int& s, int& d) {
    if (is64) {
        const long long* p = (const long long*)ei;
        s = (int)p[e];
        d = (int)p[E + e];
    } else {
        const int* p = (const int*)ei;
        s = p[e];
        d = p[E + e];
    }
}

// ---------------- CSR build ----------------
__global__ void k_zero_cnt() {
    int i = blockIdx.x * blockDim.x + threadIdx.x;
    if (i < NODES) g_cnt[i] = 0;
}

__global__ void k_count(const void* __restrict__ ei, int E) {
    int is64 = g_is64;
    int e = blockIdx.x * blockDim.x + threadIdx.x;
    if (e < E) {
        int s, d;
        get_edge(ei, E, e, is64, s, d);
        atomicAdd(&g_cnt[d], 1);
    }
}

// inclusive scan per 1024-block
__global__ void k_scan1(int n) {
    __shared__ int s[1024];
    int i = blockIdx.x * 1024 + threadIdx.x;
    s[threadIdx.x] = (i < n) ? g_cnt[i] : 0;
    __syncthreads();
    for (int off = 1; off < 1024; off <<= 1) {
        int t = (threadIdx.x >= (unsigned)off) ? s[threadIdx.x - off] : 0;
        __syncthreads();
        s[threadIdx.x] += t;
        __syncthreads();
    }
    if (i < n) g_rowptr[i] = s[threadIdx.x];
    if (threadIdx.x == 1023) g_bsum[blockIdx.x] = s[1023];
}

__global__ void k_scan2(int nb) {
    int acc = 0;
    for (int b = 0; b < nb; b++) { g_boff[b] = acc; acc += g_bsum[b]; }
}

__global__ void k_scan3(int n) {
    int i = blockIdx.x * blockDim.x + threadIdx.x;
    if (i < n) {
        int c = g_cnt[i];
        g_rowptr[i] = g_rowptr[i] - c + g_boff[i >> 10];   // exclusive start
        g_dinv[i]   = rsqrtf((float)(c + 1));              // +1 self-loop
        g_cursor[i] = 0;
    }
}

__global__ void k_fill(const void* __restrict__ ei, int E) {
    int is64 = g_is64;
    int e = blockIdx.x * blockDim.x + threadIdx.x;
    if (e < E) {
        int s, d;
        get_edge(ei, E, e, is64, s, d);
        int pos = g_rowptr[d] + atomicAdd(&g_cursor[d], 1);
        g_csr[pos] = s;
    }
}

// ---------------- GEMM: Out[r, :] = dinv[r] * (X[r, :] @ W)  (K = 128) ------
// BM = 64 rows/block, full-width NOUT, 256 threads, 4-row x (NOUT/16)-col tiles.
template <int NOUT>
__global__ void k_gemm(const float* __restrict__ X, const float* __restrict__ W,
                       float* __restrict__ Out) {
    extern __shared__ float smem[];
    float* Ws = smem;                 // [128][NOUT]
    float* Xs = smem + 128 * NOUT;    // [64][132]
    const int XS_LD = 132;
    const int TC = NOUT / 16;         // cols per thread (8 or 4)

    int tid  = threadIdx.x;           // 256 threads
    int row0 = blockIdx.x * 64;

    // stage W (row-major [128][NOUT], contiguous)
    for (int i = tid; i < 128 * NOUT / 4; i += 256)
        ((float4*)Ws)[i] = ((const float4*)W)[i];

    // stage X tile (64 x 128), zero-padded at the tail block
    for (int i = tid; i < 64 * 32; i += 256) {
        int r  = i >> 5;
        int c4 = i & 31;
        float4 v = make_float4(0.f, 0.f, 0.f, 0.f);
        if (row0 + r < NODES)
            v = *(const float4*)&X[(size_t)(row0 + r) * 128 + c4 * 4];
        *(float4*)&Xs[r * XS_LD + c4 * 4] = v;
    }
    __syncthreads();

    int tx  = tid & 15;
    int ty  = tid >> 4;
    int col = tx * TC;
    int rr  = ty * 4;

    float acc[4][TC];
#pragma unroll
    for (int i = 0; i < 4; i++)
#pragma unroll
        for (int j = 0; j < TC; j++) acc[i][j] = 0.f;

#pragma unroll 8
    for (int k = 0; k < 128; k++) {
        float a0 = Xs[(rr + 0) * XS_LD + k];
        float a1 = Xs[(rr + 1) * XS_LD + k];
        float a2 = Xs[(rr + 2) * XS_LD + k];
        float a3 = Xs[(rr + 3) * XS_LD + k];
        float4 w0 = *(float4*)&Ws[k * NOUT + col];
        acc[0][0] += a0 * w0.x; acc[0][1] += a0 * w0.y; acc[0][2] += a0 * w0.z; acc[0][3] += a0 * w0.w;
        acc[1][0] += a1 * w0.x; acc[1][1] += a1 * w0.y; acc[1][2] += a1 * w0.z; acc[1][3] += a1 * w0.w;
        acc[2][0] += a2 * w0.x; acc[2][1] += a2 * w0.y; acc[2][2] += a2 * w0.z; acc[2][3] += a2 * w0.w;
        acc[3][0] += a3 * w0.x; acc[3][1] += a3 * w0.y; acc[3][2] += a3 * w0.z; acc[3][3] += a3 * w0.w;
        if (TC == 8) {
            float4 w1 = *(float4*)&Ws[k * NOUT + col + 4];
            acc[0][4] += a0 * w1.x; acc[0][5] += a0 * w1.y; acc[0][6] += a0 * w1.z; acc[0][7] += a0 * w1.w;
            acc[1][4] += a1 * w1.x; acc[1][5] += a1 * w1.y; acc[1][6] += a1 * w1.z; acc[1][7] += a1 * w1.w;
            acc[2][4] += a2 * w1.x; acc[2][5] += a2 * w1.y; acc[2][6] += a2 * w1.z; acc[2][7] += a2 * w1.w;
            acc[3][4] += a3 * w1.x; acc[3][5] += a3 * w1.y; acc[3][6] += a3 * w1.z; acc[3][7] += a3 * w1.w;
        }
    }

#pragma unroll
    for (int i = 0; i < 4; i++) {
        int r = row0 + rr + i;
        if (r < NODES) {
            float sc = g_dinv[r];
#pragma unroll
            for (int j4 = 0; j4 < TC / 4; j4++) {
                float4 v;
                v.x = acc[i][j4 * 4 + 0] * sc;
                v.y = acc[i][j4 * 4 + 1] * sc;
                v.z = acc[i][j4 * 4 + 2] * sc;
                v.w = acc[i][j4 * 4 + 3] * sc;
                *(float4*)&Out[(size_t)r * NOUT + col + j4 * 4] = v;
            }
        }
    }
}

// ---------------- aggregation: out[d] = dinv[d]*(sum_in hs[s] + hs[d]) + b --
// one warp per node; lane owns F/32 contiguous floats.
template <int F, bool RELU>
__global__ void k_agg(const float* __restrict__ hs, const float* __restrict__ bias,
                      float* __restrict__ out) {
    const int VEC = F / 32;   // 4 or 2
    int gwarp = (blockIdx.x * blockDim.x + threadIdx.x) >> 5;
    int lane  = threadIdx.x & 31;
    if (gwarp >= NODES) return;
    int node = gwarp;

    float acc[VEC];
    {   // self-loop term
        const float* p = hs + (size_t)node * F + lane * VEC;
        if (VEC == 4) {
            float4 v = *(const float4*)p;
            acc[0] = v.x; acc[1] = v.y; acc[2] = v.z; acc[3] = v.w;
        } else {
            float2 v = *(const float2*)p;
            acc[0] = v.x; acc[1] = v.y;
        }
    }

    int beg = g_rowptr[node];
    int cnt = g_cnt[node];
    for (int base = 0; base < cnt; base += 32) {
        int idx = 0;
        if (base + lane < cnt) idx = g_csr[beg + base + lane];
        int m = min(32, cnt - base);
        for (int j = 0; j < m; j++) {
            int s = __shfl_sync(0xffffffffu, idx, j);
            const float* p = hs + (size_t)s * F + lane * VEC;
            if (VEC == 4) {
                float4 v = *(const float4*)p;
                acc[0] += v.x; acc[1] += v.y; acc[2] += v.z; acc[3] += v.w;
            } else {
                float2 v = *(const float2*)p;
                acc[0] += v.x; acc[1] += v.y;
            }
        }
    }

    float dn = g_dinv[node];
    float* o = out + (size_t)node * F + lane * VEC;
    if (VEC == 4) {
        float4 r;
        r.x = dn * acc[0] + bias[lane * 4 + 0];
        r.y = dn * acc[1] + bias[lane * 4 + 1];
        r.z = dn * acc[2] + bias[lane * 4 + 2];
        r.w = dn * acc[3] + bias[lane * 4 + 3];
        if (RELU) {
            r.x = fmaxf(r.x, 0.f); r.y = fmaxf(r.y, 0.f);
            r.z = fmaxf(r.z, 0.f); r.w = fmaxf(r.w, 0.f);
        }
        *(float4*)o = r;
    } else {
        float2 r;
        r.x = dn * acc[0] + bias[lane * 2 + 0];
        r.y = dn * acc[1] + bias[lane * 2 + 1];
        if (RELU) { r.x = fmaxf(r.x, 0.f); r.y = fmaxf(r.y, 0.f); }
        *(float2*)o = r;
    }
}

// ---------------- launch ----------------
extern "C" void kernel_launch(void* const* d_in, const int* in_sizes, int n_in,
                              void* d_out, int out_size) {
    const float* x  = (const float*)d_in[0];
    const void*  ei = d_in[1];
    const float* W1 = (const float*)d_in[2];
    const float* b1 = (const float*)d_in[3];
    const float* W2 = (const float*)d_in[4];
    const float* b2 = (const float*)d_in[5];
    float* out = (float*)d_out;

    int E = in_sizes[1] / 2;   // 1,600,000

    static bool attr_done = false;
    if (!attr_done) {
        cudaFuncSetAttribute(k_gemm<F_HID>, cudaFuncAttributeMaxDynamicSharedMemorySize,
                             (128 * F_HID + 64 * 132) * 4);
        cudaFuncSetAttribute(k_gemm<F_OUT>, cudaFuncAttributeMaxDynamicSharedMemorySize,
                             (128 * F_OUT + 64 * 132) * 4);
        attr_done = true;
    }

    int nScanBlocks = (NODES + 1023) / 1024;        // 98
    int nNodeBlocks = (NODES + 255) / 256;          // 391
    int nEdgeBlocks = (E + 255) / 256;              // 6250
    int nGemmBlocks = (NODES + 63) / 64;            // 1563
    int nAggBlocks  = (NODES * 32 + 255) / 256;     // 12500

    // CSR build (per call: must be stateless/deterministic work)
    k_detect<<<1, 256>>>((const unsigned int*)ei);
    k_zero_cnt<<<nNodeBlocks, 256>>>();
    k_count<<<nEdgeBlocks, 256>>>(ei, E);
    k_scan1<<<nScanBlocks, 1024>>>(NODES);
    k_scan2<<<1, 1>>>(nScanBlocks);
    k_scan3<<<nNodeBlocks, 256>>>(NODES);
    k_fill<<<nEdgeBlocks, 256>>>(ei, E);

    // layer 1
    k_gemm<F_HID><<<nGemmBlocks, 256, (128 * F_HID + 64 * 132) * 4>>>(x, W1, g_hs1);
    k_agg<F_HID, true><<<nAggBlocks, 256>>>(g_hs1, b1, g_y1);

    // layer 2
    k_gemm<F_OUT><<<nGemmBlocks, 256, (128 * F_OUT + 64 * 132) * 4>>>(g_y1, W2, g_hs2);
    k_agg<F_OUT, false><<<nAggBlocks, 256>>>(g_hs2, b2, out);
}

// round 2
// speedup vs baseline: 1.0005x; 1.0005x over previous
#include <cuda_runtime.h>
#include <cuda_bf16.h>

#define NODES 100000
#define EDGES_MAX 1600000
#define F_HID 128
#define F_OUT 64

// ---------------- scratch (device globals: allocation-free) ----------------
__device__ int   g_is64;
__device__ int   g_cnt[NODES];
__device__ int   g_cursor[NODES];
__device__ int   g_rowptr[NODES];
__device__ float g_dinv[NODES];
__device__ int   g_csr[EDGES_MAX];
__device__ float g_hs1[(size_t)NODES * F_HID];   // dinv * (x @ W1)
__device__ float g_y1 [(size_t)NODES * F_HID];   // relu(agg1 + b1)
__device__ float g_hs2[(size_t)NODES * F_OUT];   // dinv * (y1 @ W2)
__device__ int   g_bsum[128];
__device__ int   g_boff[128];

// ---------------- dtype detection: int64 vs int32 edge_index ----------------
// For an int64 array of nonneg values < 100000, every odd 32-bit word is 0.
// For int32 random values in [0,1e5), P(word==0) = 1e-5 -> 1024 in a row ~ impossible.
__global__ void k_detect(const unsigned int* __restrict__ w) {
    __shared__ int ok;
    if (threadIdx.x == 0) ok = 1;
    __syncthreads();
    int bad = 0;
    for (int i = threadIdx.x; i < 1024; i += blockDim.x)
        if (w[2 * i + 1] != 0u) bad = 1;
    if (bad) atomicAnd(&ok, 0);
    __syncthreads();
    if (threadIdx.x == 0) g_is64 = ok;
}

__device__ __forceinline__ void get_edge(const void* ei, int E, int e, int is64,
                                         int& s, int& d) {
    if (is64) {
        const long long* p = (const long long*)ei;
        s = (int)p[e];
        d = (int)p[E + e];
    } else {
        const int* p = (const int*)ei;
        s = p[e];
        d = p[E + e];
    }
}

// ---------------- CSR build ----------------
__global__ void k_zero_cnt() {
    int i = blockIdx.x * blockDim.x + threadIdx.x;
    if (i < NODES) g_cnt[i] = 0;
}

__global__ void k_count(const void* __restrict__ ei, int E) {
    int is64 = g_is64;
    int e = blockIdx.x * blockDim.x + threadIdx.x;
    if (e < E) {
        int s, d;
        get_edge(ei, E, e, is64, s, d);
        atomicAdd(&g_cnt[d], 1);
    }
}

// inclusive scan per 1024-block
__global__ void k_scan1(int n) {
    __shared__ int s[1024];
    int i = blockIdx.x * 1024 + threadIdx.x;
    s[threadIdx.x] = (i < n) ? g_cnt[i] : 0;
    __syncthreads();
    for (int off = 1; off < 1024; off <<= 1) {
        int t = (threadIdx.x >= (unsigned)off) ? s[threadIdx.x - off] : 0;
        __syncthreads();
        s[threadIdx.x] += t;
        __syncthreads();
    }
    if (i < n) g_rowptr[i] = s[threadIdx.x];
    if (threadIdx.x == 1023) g_bsum[blockIdx.x] = s[1023];
}

__global__ void k_scan2(int nb) {
    int acc = 0;
    for (int b = 0; b < nb; b++) { g_boff[b] = acc; acc += g_bsum[b]; }
}

__global__ void k_scan3(int n) {
    int i = blockIdx.x * blockDim.x + threadIdx.x;
    if (i < n) {
        int c = g_cnt[i];
        g_rowptr[i] = g_rowptr[i] - c + g_boff[i >> 10];   // exclusive start
        g_dinv[i]   = rsqrtf((float)(c + 1));              // +1 self-loop
        g_cursor[i] = 0;
    }
}

__global__ void k_fill(const void* __restrict__ ei, int E) {
    int is64 = g_is64;
    int e = blockIdx.x * blockDim.x + threadIdx.x;
    if (e < E) {
        int s, d;
        get_edge(ei, E, e, is64, s, d);
        int pos = g_rowptr[d] + atomicAdd(&g_cursor[d], 1);
        g_csr[pos] = s;
    }
}

// ---------------- GEMM: Out[r, :] = dinv[r] * (X[r, :] @ W)  (K = 128) ------
// BM = 64 rows/block, full-width NOUT, 256 threads, 4-row x (NOUT/16)-col tiles.
template <int NOUT>
__global__ void k_gemm(const float* __restrict__ X, const float* __restrict__ W,
                       float* __restrict__ Out) {
    extern __shared__ float smem[];
    float* Ws = smem;                 // [128][NOUT]
    float* Xs = smem + 128 * NOUT;    // [64][132]
    const int XS_LD = 132;
    const int TC = NOUT / 16;         // cols per thread (8 or 4)

    int tid  = threadIdx.x;           // 256 threads
    int row0 = blockIdx.x * 64;

    // stage W (row-major [128][NOUT], contiguous)
    for (int i = tid; i < 128 * NOUT / 4; i += 256)
        ((float4*)Ws)[i] = ((const float4*)W)[i];

    // stage X tile (64 x 128), zero-padded at the tail block
    for (int i = tid; i < 64 * 32; i += 256) {
        int r  = i >> 5;
        int c4 = i & 31;
        float4 v = make_float4(0.f, 0.f, 0.f, 0.f);
        if (row0 + r < NODES)
            v = *(const float4*)&X[(size_t)(row0 + r) * 128 + c4 * 4];
        *(float4*)&Xs[r * XS_LD + c4 * 4] = v;
    }
    __syncthreads();

    int tx  = tid & 15;
    int ty  = tid >> 4;
    int col = tx * TC;
    int rr  = ty * 4;

    float acc[4][TC];
#pragma unroll
    for (int i = 0; i < 4; i++)
#pragma unroll
        for (int j = 0; j < TC; j++) acc[i][j] = 0.f;

#pragma unroll 8
    for (int k = 0; k < 128; k++) {
        float a0 = Xs[(rr + 0) * XS_LD + k];
        float a1 = Xs[(rr + 1) * XS_LD + k];
        float a2 = Xs[(rr + 2) * XS_LD + k];
        float a3 = Xs[(rr + 3) * XS_LD + k];
        float4 w0 = *(float4*)&Ws[k * NOUT + col];
        acc[0][0] += a0 * w0.x; acc[0][1] += a0 * w0.y; acc[0][2] += a0 * w0.z; acc[0][3] += a0 * w0.w;
        acc[1][0] += a1 * w0.x; acc[1][1] += a1 * w0.y; acc[1][2] += a1 * w0.z; acc[1][3] += a1 * w0.w;
        acc[2][0] += a2 * w0.x; acc[2][1] += a2 * w0.y; acc[2][2] += a2 * w0.z; acc[2][3] += a2 * w0.w;
        acc[3][0] += a3 * w0.x; acc[3][1] += a3 * w0.y; acc[3][2] += a3 * w0.z; acc[3][3] += a3 * w0.w;
        if (TC == 8) {
            float4 w1 = *(float4*)&Ws[k * NOUT + col + 4];
            acc[0][4] += a0 * w1.x; acc[0][5] += a0 * w1.y; acc[0][6] += a0 * w1.z; acc[0][7] += a0 * w1.w;
            acc[1][4] += a1 * w1.x; acc[1][5] += a1 * w1.y; acc[1][6] += a1 * w1.z; acc[1][7] += a1 * w1.w;
            acc[2][4] += a2 * w1.x; acc[2][5] += a2 * w1.y; acc[2][6] += a2 * w1.z; acc[2][7] += a2 * w1.w;
            acc[3][4] += a3 * w1.x; acc[3][5] += a3 * w1.y; acc[3][6] += a3 * w1.z; acc[3][7] += a3 * w1.w;
        }
    }

#pragma unroll
    for (int i = 0; i < 4; i++) {
        int r = row0 + rr + i;
        if (r < NODES) {
            float sc = g_dinv[r];
#pragma unroll
            for (int j4 = 0; j4 < TC / 4; j4++) {
                float4 v;
                v.x = acc[i][j4 * 4 + 0] * sc;
                v.y = acc[i][j4 * 4 + 1] * sc;
                v.z = acc[i][j4 * 4 + 2] * sc;
                v.w = acc[i][j4 * 4 + 3] * sc;
                *(float4*)&Out[(size_t)r * NOUT + col + j4 * 4] = v;
            }
        }
    }
}

// ---------------- aggregation: out[d] = dinv[d]*(sum_in hs[s] + hs[d]) + b --
// one warp per node; lane owns F/32 contiguous floats.
template <int F, bool RELU>
__global__ void k_agg(const float* __restrict__ hs, const float* __restrict__ bias,
                      float* __restrict__ out) {
    const int VEC = F / 32;   // 4 or 2
    int gwarp = (blockIdx.x * blockDim.x + threadIdx.x) >> 5;
    int lane  = threadIdx.x & 31;
    if (gwarp >= NODES) return;
    int node = gwarp;

    float acc[VEC];
    {   // self-loop term
        const float* p = hs + (size_t)node * F + lane * VEC;
        if (VEC == 4) {
            float4 v = *(const float4*)p;
            acc[0] = v.x; acc[1] = v.y; acc[2] = v.z; acc[3] = v.w;
        } else {
            float2 v = *(const float2*)p;
            acc[0] = v.x; acc[1] = v.y;
        }
    }

    int beg = g_rowptr[node];
    int cnt = g_cnt[node];
    for (int base = 0; base < cnt; base += 32) {
        int idx = 0;
        if (base + lane < cnt) idx = g_csr[beg + base + lane];
        int m = min(32, cnt - base);
        for (int j = 0; j < m; j++) {
            int s = __shfl_sync(0xffffffffu, idx, j);
            const float* p = hs + (size_t)s * F + lane * VEC;
            if (VEC == 4) {
                float4 v = *(const float4*)p;
                acc[0] += v.x; acc[1] += v.y; acc[2] += v.z; acc[3] += v.w;
            } else {
                float2 v = *(const float2*)p;
                acc[0] += v.x; acc[1] += v.y;
            }
        }
    }

    float dn = g_dinv[node];
    float* o = out + (size_t)node * F + lane * VEC;
    if (VEC == 4) {
        float4 r;
        r.x = dn * acc[0] + bias[lane * 4 + 0];
        r.y = dn * acc[1] + bias[lane * 4 + 1];
        r.z = dn * acc[2] + bias[lane * 4 + 2];
        r.w = dn * acc[3] + bias[lane * 4 + 3];
        if (RELU) {
            r.x = fmaxf(r.x, 0.f); r.y = fmaxf(r.y, 0.f);
            r.z = fmaxf(r.z, 0.f); r.w = fmaxf(r.w, 0.f);
        }
        *(float4*)o = r;
    } else {
        float2 r;
        r.x = dn * acc[0] + bias[lane * 2 + 0];
        r.y = dn * acc[1] + bias[lane * 2 + 1];
        if (RELU) { r.x = fmaxf(r.x, 0.f); r.y = fmaxf(r.y, 0.f); }
        *(float2*)o = r;
    }
}

// ---------------- launch ----------------
extern "C" void kernel_launch(void* const* d_in, const int* in_sizes, int n_in,
                              void* d_out, int out_size) {
    const float* x  = (const float*)d_in[0];
    const void*  ei = d_in[1];
    const float* W1 = (const float*)d_in[2];
    const float* b1 = (const float*)d_in[3];
    const float* W2 = (const float*)d_in[4];
    const float* b2 = (const float*)d_in[5];
    float* out = (float*)d_out;

    int E = in_sizes[1] / 2;   // 1,600,000

    static bool attr_done = false;
    if (!attr_done) {
        cudaFuncSetAttribute(k_gemm<F_HID>, cudaFuncAttributeMaxDynamicSharedMemorySize,
                             (128 * F_HID + 64 * 132) * 4);
        cudaFuncSetAttribute(k_gemm<F_OUT>, cudaFuncAttributeMaxDynamicSharedMemorySize,
                             (128 * F_OUT + 64 * 132) * 4);
        attr_done = true;
    }

    int nScanBlocks = (NODES + 1023) / 1024;        // 98
    int nNodeBlocks = (NODES + 255) / 256;          // 391
    int nEdgeBlocks = (E + 255) / 256;              // 6250
    int nGemmBlocks = (NODES + 63) / 64;            // 1563
    int nAggBlocks  = (NODES * 32 + 255) / 256;     // 12500

    // CSR build (per call: must be stateless/deterministic work)
    k_detect<<<1, 256>>>((const unsigned int*)ei);
    k_zero_cnt<<<nNodeBlocks, 256>>>();
    k_count<<<nEdgeBlocks, 256>>>(ei, E);
    k_scan1<<<nScanBlocks, 1024>>>(NODES);
    k_scan2<<<1, 1>>>(nScanBlocks);
    k_scan3<<<nNodeBlocks, 256>>>(NODES);
    k_fill<<<nEdgeBlocks, 256>>>(ei, E);

    // layer 1
    k_gemm<F_HID><<<nGemmBlocks, 256, (128 * F_HID + 64 * 132) * 4>>>(x, W1, g_hs1);
    k_agg<F_HID, true><<<nAggBlocks, 256>>>(g_hs1, b1, g_y1);

    // layer 2
    k_gemm<F_OUT><<<nGemmBlocks, 256, (128 * F_OUT + 64 * 132) * 4>>>(g_y1, W2, g_hs2);
    k_agg<F_OUT, false><<<nAggBlocks, 256>>>(g_hs2, b2, out);
}